// round 6
// baseline (speedup 1.0000x reference)
#include <cuda_runtime.h>
#include <math.h>

#define N_NODES 8192
#define D 256
#define MAXNNZ 128

// Scratch: ELL adjacency (4 matrices) + 8 feature buffers [8192,256] fp32
__device__ int   g_cols[4][N_NODES * MAXNNZ];
__device__ int   g_len[4][N_NODES];
__device__ float g_buf[8][N_NODES * D];

// ---------------------------------------------------------------------------
// tf32 helpers
// ---------------------------------------------------------------------------
__device__ __forceinline__ unsigned f2tf32(float f) {
    unsigned r;
    asm("cvt.rna.tf32.f32 %0, %1;" : "=r"(r) : "f"(f));
    return r;
}

__device__ __forceinline__ void mma_tf32(float* c, const unsigned* a, const unsigned* b) {
    asm volatile(
        "mma.sync.aligned.m16n8k8.row.col.f32.tf32.tf32.f32 "
        "{%0,%1,%2,%3}, {%4,%5,%6,%7}, {%8,%9}, {%0,%1,%2,%3};"
        : "+f"(c[0]), "+f"(c[1]), "+f"(c[2]), "+f"(c[3])
        : "r"(a[0]), "r"(a[1]), "r"(a[2]), "r"(a[3]), "r"(b[0]), "r"(b[1]));
}

#define SST 20   // smem row stride (floats)

// ---------------------------------------------------------------------------
// GEMM block body: one 128x128 output tile of Ci = X @ Wi^T + bi.
// gemm_id in [0,768): nblk = id%12 -> (mat = nblk>>1, n0 = (nblk&1)*128),
// m0 = (id/12)*128. mats 0..2 use X0, 3..5 use X1.
// BK=16 double-buffered, 8 warps x (32x64) m16n8k8 tf32.
// ---------------------------------------------------------------------------
__device__ __forceinline__ void gemm_body(
    int gemm_id, float (*As)[128 * SST], float (*Bs)[128 * SST],
    const float* __restrict__ X0, const float* __restrict__ X1,
    const float* __restrict__ W0, const float* __restrict__ W1, const float* __restrict__ W2,
    const float* __restrict__ W3, const float* __restrict__ W4, const float* __restrict__ W5,
    const float* __restrict__ b0, const float* __restrict__ b1, const float* __restrict__ b2,
    const float* __restrict__ b3, const float* __restrict__ b4, const float* __restrict__ b5,
    float* __restrict__ C0, float* __restrict__ C1, float* __restrict__ C2,
    float* __restrict__ C3, float* __restrict__ C4, float* __restrict__ C5, int K)
{
    int tid  = threadIdx.x;
    int nblk = gemm_id % 12;
    int mat  = nblk >> 1;
    int n0   = (nblk & 1) * 128;
    int m0   = (gemm_id / 12) * 128;

    const float* X = (mat < 3) ? X0 : X1;
    const float* W = (mat == 0) ? W0 : (mat == 1) ? W1 : (mat == 2) ? W2 :
                     (mat == 3) ? W3 : (mat == 4) ? W4 : W5;
    const float* bias = (mat == 0) ? b0 : (mat == 1) ? b1 : (mat == 2) ? b2 :
                        (mat == 3) ? b3 : (mat == 4) ? b4 : b5;
    float* C = (mat == 0) ? C0 : (mat == 1) ? C1 : (mat == 2) ? C2 :
               (mat == 3) ? C3 : (mat == 4) ? C4 : C5;

    int wid = tid >> 5, lane = tid & 31;
    int wm = (wid >> 1) * 32;
    int wn = (wid & 1) * 64;
    int gid = lane >> 2;
    int tg  = lane & 3;

    float acc[2][8][4];
    #pragma unroll
    for (int i = 0; i < 2; i++)
        #pragma unroll
        for (int j = 0; j < 8; j++)
            #pragma unroll
            for (int k = 0; k < 4; k++) acc[i][j][k] = 0.0f;

    int lrow = tid >> 2;
    int lc4  = (tid & 3) * 4;

    int nkc = K >> 4;
    float4 xv[2], wv[2];

    #pragma unroll
    for (int i = 0; i < 2; i++) {
        int r = i * 64 + lrow;
        xv[i] = *(const float4*)(X + (size_t)(m0 + r) * K + lc4);
        wv[i] = *(const float4*)(W + (size_t)(n0 + r) * K + lc4);
    }
    #pragma unroll
    for (int i = 0; i < 2; i++) {
        int base = (i * 64 + lrow) * SST + lc4;
        As[0][base + 0] = __uint_as_float(f2tf32(xv[i].x));
        As[0][base + 1] = __uint_as_float(f2tf32(xv[i].y));
        As[0][base + 2] = __uint_as_float(f2tf32(xv[i].z));
        As[0][base + 3] = __uint_as_float(f2tf32(xv[i].w));
        Bs[0][base + 0] = __uint_as_float(f2tf32(wv[i].x));
        Bs[0][base + 1] = __uint_as_float(f2tf32(wv[i].y));
        Bs[0][base + 2] = __uint_as_float(f2tf32(wv[i].z));
        Bs[0][base + 3] = __uint_as_float(f2tf32(wv[i].w));
    }
    __syncthreads();

    for (int kc = 0; kc < nkc; kc++) {
        int buf = kc & 1;
        bool more = (kc + 1) < nkc;
        if (more) {
            int koff = (kc + 1) * 16;
            #pragma unroll
            for (int i = 0; i < 2; i++) {
                int r = i * 64 + lrow;
                xv[i] = *(const float4*)(X + (size_t)(m0 + r) * K + koff + lc4);
                wv[i] = *(const float4*)(W + (size_t)(n0 + r) * K + koff + lc4);
            }
        }
        #pragma unroll
        for (int k8 = 0; k8 < 16; k8 += 8) {
            unsigned a[2][4];
            #pragma unroll
            for (int mt = 0; mt < 2; mt++) {
                int r = wm + mt * 16 + gid;
                a[mt][0] = __float_as_uint(As[buf][(r)     * SST + k8 + tg]);
                a[mt][1] = __float_as_uint(As[buf][(r + 8) * SST + k8 + tg]);
                a[mt][2] = __float_as_uint(As[buf][(r)     * SST + k8 + tg + 4]);
                a[mt][3] = __float_as_uint(As[buf][(r + 8) * SST + k8 + tg + 4]);
            }
            #pragma unroll
            for (int nt = 0; nt < 8; nt++) {
                int rn = wn + nt * 8 + gid;
                unsigned b[2];
                b[0] = __float_as_uint(Bs[buf][rn * SST + k8 + tg]);
                b[1] = __float_as_uint(Bs[buf][rn * SST + k8 + tg + 4]);
                mma_tf32(acc[0][nt], a[0], b);
                mma_tf32(acc[1][nt], a[1], b);
            }
        }
        __syncthreads();
        if (more) {
            int ob = buf ^ 1;
            #pragma unroll
            for (int i = 0; i < 2; i++) {
                int base = (i * 64 + lrow) * SST + lc4;
                As[ob][base + 0] = __uint_as_float(f2tf32(xv[i].x));
                As[ob][base + 1] = __uint_as_float(f2tf32(xv[i].y));
                As[ob][base + 2] = __uint_as_float(f2tf32(xv[i].z));
                As[ob][base + 3] = __uint_as_float(f2tf32(xv[i].w));
                Bs[ob][base + 0] = __uint_as_float(f2tf32(wv[i].x));
                Bs[ob][base + 1] = __uint_as_float(f2tf32(wv[i].y));
                Bs[ob][base + 2] = __uint_as_float(f2tf32(wv[i].z));
                Bs[ob][base + 3] = __uint_as_float(f2tf32(wv[i].w));
            }
            __syncthreads();
        }
    }

    #pragma unroll
    for (int mt = 0; mt < 2; mt++) {
        #pragma unroll
        for (int nt = 0; nt < 8; nt++) {
            int col = n0 + wn + nt * 8 + tg * 2;
            float2 bv = *(const float2*)(bias + col);
            int r0 = m0 + wm + mt * 16 + gid;
            float2 o0 = {acc[mt][nt][0] + bv.x, acc[mt][nt][1] + bv.y};
            float2 o1 = {acc[mt][nt][2] + bv.x, acc[mt][nt][3] + bv.y};
            *(float2*)(C + (size_t)r0 * D + col)       = o0;
            *(float2*)(C + (size_t)(r0 + 8) * D + col) = o1;
        }
    }
}

// ---------------------------------------------------------------------------
// Extract block body: 8 warps, each compacts one adjacency row to ELL.
// eid in [0,4096): row_global = eid*8 + wid over 4*8192 rows.
// ---------------------------------------------------------------------------
__device__ __forceinline__ void extract_body(
    int eid,
    const float* __restrict__ a0, const float* __restrict__ a1,
    const float* __restrict__ a2, const float* __restrict__ a3)
{
    int wid  = threadIdx.x >> 5;
    int lane = threadIdx.x & 31;
    int rg   = eid * 8 + wid;
    int mat  = rg >> 13;
    int row  = rg & (N_NODES - 1);
    const float* A = (mat == 0) ? a0 : (mat == 1) ? a1 : (mat == 2) ? a2 : a3;
    const float* arow = A + (size_t)row * N_NODES;
    int* cols = &g_cols[mat][row * MAXNNZ];
    int base = 0;
    for (int c0 = 0; c0 < N_NODES; c0 += 128) {
        float4 v = *(const float4*)(arow + c0 + lane * 4);
        float vv[4] = {v.x, v.y, v.z, v.w};
        #pragma unroll
        for (int j = 0; j < 4; j++) {
            bool nz = (vv[j] != 0.0f);
            unsigned m = __ballot_sync(0xffffffffu, nz);
            if (nz) {
                int off = base + __popc(m & ((1u << lane) - 1u));
                if (off < MAXNNZ) cols[off] = c0 + lane * 4 + j;
            }
            base += __popc(m);
        }
    }
    if (lane == 0) g_len[mat][row] = base < MAXNNZ ? base : MAXNNZ;
}

// ---------------------------------------------------------------------------
// Layer-1 heterogeneous kernel: 4864 blocks.
// blockIdx.x % 19 < 3  -> GEMM block (exactly 768 = 256*3)
// else                 -> extract block (exactly 4096 = 256*16)
// Interleaving guarantees every scheduling wave mixes DRAM-bound extract
// blocks with tensor-bound GEMM blocks -> overlap within one launch.
// ---------------------------------------------------------------------------
__global__ void __launch_bounds__(256) gemm6_extract_kernel(
    const float* __restrict__ X0, const float* __restrict__ X1,
    const float* __restrict__ W0, const float* __restrict__ W1, const float* __restrict__ W2,
    const float* __restrict__ W3, const float* __restrict__ W4, const float* __restrict__ W5,
    const float* __restrict__ b0, const float* __restrict__ b1, const float* __restrict__ b2,
    const float* __restrict__ b3, const float* __restrict__ b4, const float* __restrict__ b5,
    float* __restrict__ C0, float* __restrict__ C1, float* __restrict__ C2,
    float* __restrict__ C3, float* __restrict__ C4, float* __restrict__ C5, int K,
    const float* __restrict__ a0, const float* __restrict__ a1,
    const float* __restrict__ a2, const float* __restrict__ a3)
{
    __shared__ float As[2][128 * SST];
    __shared__ float Bs[2][128 * SST];
    int g = blockIdx.x;
    int r = g % 19;
    int q = g / 19;
    if (r < 3) {
        gemm_body(q * 3 + r, As, Bs, X0, X1, W0, W1, W2, W3, W4, W5,
                  b0, b1, b2, b3, b4, b5, C0, C1, C2, C3, C4, C5, K);
    } else {
        extract_body(q * 16 + (r - 3), a0, a1, a2, a3);
    }
}

// Plain GEMM-only kernel for layer 2 (768 blocks, 1D).
__global__ void __launch_bounds__(256) gemm6_kernel(
    const float* __restrict__ X0, const float* __restrict__ X1,
    const float* __restrict__ W0, const float* __restrict__ W1, const float* __restrict__ W2,
    const float* __restrict__ W3, const float* __restrict__ W4, const float* __restrict__ W5,
    const float* __restrict__ b0, const float* __restrict__ b1, const float* __restrict__ b2,
    const float* __restrict__ b3, const float* __restrict__ b4, const float* __restrict__ b5,
    float* __restrict__ C0, float* __restrict__ C1, float* __restrict__ C2,
    float* __restrict__ C3, float* __restrict__ C4, float* __restrict__ C5, int K)
{
    __shared__ float As[2][128 * SST];
    __shared__ float Bs[2][128 * SST];
    gemm_body(blockIdx.x, As, Bs, X0, X1, W0, W1, W2, W3, W4, W5,
              b0, b1, b2, b3, b4, b5, C0, C1, C2, C3, C4, C5, K);
}

// ---------------------------------------------------------------------------
// Fused dual combine: blocks [0,2048) do config P (hp side),
// blocks [2048,4096) do config Q (hq side). float4, 64 thr/row, 4 rows/block.
// out[row,:] = act( P[row,:] + sum_A XA[c,:] + sum_B XB[c,:] ), optional L2 norm.
// ---------------------------------------------------------------------------
__global__ void __launch_bounds__(256) combine2x_kernel(
    const float* __restrict__ P0, const float* __restrict__ XA0, const float* __restrict__ XB0,
    int mA0, int mB0, float* __restrict__ out0,
    const float* __restrict__ P1, const float* __restrict__ XA1, const float* __restrict__ XB1,
    int mA1, int mB1, float* __restrict__ out1,
    int do_norm)
{
    __shared__ int sA[4][MAXNNZ];
    __shared__ int sB[4][MAXNNZ];
    __shared__ float red[4][2];

    int blk = blockIdx.x;
    const float *P, *XA, *XB;
    float* out;
    int matA, matB, rowbase;
    if (blk < 2048) {
        P = P0; XA = XA0; XB = XB0; out = out0; matA = mA0; matB = mB0;
        rowbase = blk * 4;
    } else {
        P = P1; XA = XA1; XB = XB1; out = out1; matA = mA1; matB = mB1;
        rowbase = (blk - 2048) * 4;
    }

    int tid = threadIdx.x;
    int r   = tid >> 6;
    int t   = tid & 63;
    int row = rowbase + r;

    int lenA = g_len[matA][row];
    int lenB = g_len[matB][row];
    {
        const int* cA = &g_cols[matA][row * MAXNNZ];
        const int* cB = &g_cols[matB][row * MAXNNZ];
        if (t      < lenA) sA[r][t]      = cA[t];
        if (t + 64 < lenA) sA[r][t + 64] = cA[t + 64];
        if (t      < lenB) sB[r][t]      = cB[t];
        if (t + 64 < lenB) sB[r][t + 64] = cB[t + 64];
    }
    __syncthreads();

    int c4 = t * 4;
    float4 acc = *(const float4*)(P + (size_t)row * D + c4);
    #pragma unroll 4
    for (int i = 0; i < lenA; i++) {
        float4 v = *(const float4*)(XA + (size_t)sA[r][i] * D + c4);
        acc.x += v.x; acc.y += v.y; acc.z += v.z; acc.w += v.w;
    }
    #pragma unroll 4
    for (int i = 0; i < lenB; i++) {
        float4 v = *(const float4*)(XB + (size_t)sB[r][i] * D + c4);
        acc.x += v.x; acc.y += v.y; acc.z += v.z; acc.w += v.w;
    }
    acc.x = acc.x > 0.0f ? acc.x : 0.1f * acc.x;
    acc.y = acc.y > 0.0f ? acc.y : 0.1f * acc.y;
    acc.z = acc.z > 0.0f ? acc.z : 0.1f * acc.z;
    acc.w = acc.w > 0.0f ? acc.w : 0.1f * acc.w;

    if (do_norm) {
        float s = acc.x * acc.x + acc.y * acc.y + acc.z * acc.z + acc.w * acc.w;
        #pragma unroll
        for (int off = 16; off > 0; off >>= 1)
            s += __shfl_xor_sync(0xffffffffu, s, off);
        if ((t & 31) == 0) red[r][t >> 5] = s;
        __syncthreads();
        float inv = 1.0f / (sqrtf(red[r][0] + red[r][1]) + 1e-9f);
        acc.x *= inv; acc.y *= inv; acc.z *= inv; acc.w *= inv;
    }
    *(float4*)(out + (size_t)row * D + c4) = acc;
}

// ---------------------------------------------------------------------------
extern "C" void kernel_launch(void* const* d_in, const int* in_sizes, int n_in,
                              void* d_out, int out_size)
{
    const float* hp         = (const float*)d_in[0];
    const float* hq         = (const float*)d_in[1];
    const float* a_cons     = (const float*)d_in[2];
    const float* a_prod     = (const float*)d_in[3];
    const float* a_rev_cons = (const float*)d_in[4];
    const float* a_rev_prod = (const float*)d_in[5];
    const float* w[12];
    const float* b[12];
    for (int i = 0; i < 12; i++) {
        w[i] = (const float*)d_in[6 + 2 * i];
        b[i] = (const float*)d_in[7 + 2 * i];
    }
    float* out = (float*)d_out;

    void* symp = nullptr;
    cudaGetSymbolAddress(&symp, g_buf);
    float* B0 = (float*)symp;
    #define BUF(i) (B0 + (size_t)(i) * N_NODES * D)

    // ---- layer 1 (K = 512) + adjacency ELL extract, one heterogeneous launch
    // P-side (mats 0..2): X=hp -> {wp1->BUF0, wprod1->BUF4, wrcons1->BUF5}
    // Q-side (mats 3..5): X=hq -> {wq1->BUF1, wcons1->BUF2, wrprod1->BUF3}
    // extract mats: 0=a_cons, 1=a_prod, 2=a_rev_cons, 3=a_rev_prod
    gemm6_extract_kernel<<<4864, 256>>>(
        hp, hq,
        w[0], w[4], w[5], w[1], w[2], w[3],
        b[0], b[4], b[5], b[1], b[2], b[3],
        BUF(0), BUF(4), BUF(5), BUF(1), BUF(2), BUF(3), 512,
        a_cons, a_prod, a_rev_cons, a_rev_prod);

    // hp1 = act(BUF0 + a_cons@BUF2 + a_rev_prod@BUF3) ; hq1 analogous
    combine2x_kernel<<<4096, 256>>>(
        BUF(0), BUF(2), BUF(3), 0, 3, BUF(6),
        BUF(1), BUF(4), BUF(5), 1, 2, BUF(7), 0);

    // ---- layer 2 (K = 256) ----
    gemm6_kernel<<<768, 256>>>(
        BUF(6), BUF(7),
        w[6], w[10], w[11], w[7], w[8], w[9],
        b[6], b[10], b[11], b[7], b[8], b[9],
        BUF(0), BUF(4), BUF(5), BUF(1), BUF(2), BUF(3), 256);

    combine2x_kernel<<<4096, 256>>>(
        BUF(0), BUF(2), BUF(3), 0, 3, out,
        BUF(1), BUF(4), BUF(5), 1, 2, out + (size_t)N_NODES * D, 1);
    #undef BUF
}